// round 11
// baseline (speedup 1.0000x reference)
#include <cuda_runtime.h>
#include <cuda_bf16.h>
#include <cstdint>

#define BATCH 64
#define TCAP  32
#define VOCAB 32000
#define EDIM  1024
#define DDIM  1024
#define TDEC  31
#define NG    4096
#define MROWS 2048
#define CROW  144
#define NCHUNK 16
#define NCH8  8            // int8 K-chunks (128 int8 per chunk)
#define KSPLIT 4
#define NTILES 32          // 4096 / 128

// ---------------- static scratch ----------------
__device__ int   d_sortind[BATCH];
__device__ int   d_declen[BATCH];
__device__ int   d_cnt[TDEC];
__device__ int   d_rowstart[TDEC];
__device__ int   d_Mact;
__device__ int   d_M2048 = 2048;
__device__ int   d_i64;
__device__ int   d_ncnt[NTILES];
__device__ long long d_rowout[MROWS];
__device__ __align__(16) float d_gatesx[TCAP * BATCH * NG];   // gate-PACKED cols
__device__ __align__(16) float d_biasPk[NG];
__device__ __align__(16) float d_c[BATCH * DDIM];
__device__ __align__(16) float d_part[KSPLIT][BATCH][NG];
__device__ __align__(16) float d_wscale[VOCAB];               // wn/127 per fc row
// chunked + padded bf16 operands: [chunk16][row][144B]
__device__ __align__(16) char d_XhiC [NCHUNK * MROWS * CROW];
__device__ __align__(16) char d_XloC [NCHUNK * MROWS * CROW];
__device__ __align__(16) char d_WihHiC[NCHUNK * NG * CROW];   // gate-packed rows
__device__ __align__(16) char d_WihLoC[NCHUNK * NG * CROW];
__device__ __align__(16) char d_WhhHiC[NCHUNK * NG * CROW];
__device__ __align__(16) char d_WhhLoC[NCHUNK * NG * CROW];
// int8 two-level operands for fc: [chunk8][row][144B] (128 int8 payload/row)
__device__ __align__(16) char d_HP1C[NCH8 * MROWS * CROW];
__device__ __align__(16) char d_HP2C[NCH8 * MROWS * CROW];
__device__ __align__(16) char d_WfcP1C[NCH8 * VOCAB * CROW];
__device__ __align__(16) char d_WfcP2C[NCH8 * VOCAB * CROW];
// ping-pong h (bf16 hi/lo), chunked [2][chunk16][64][144B]
__device__ __align__(16) char d_HpHi[2][NCHUNK * BATCH * CROW];
__device__ __align__(16) char d_HpLo[2][NCHUNK * BATCH * CROW];

__device__ __forceinline__ float sigmf(float x) { return 1.0f / (1.0f + expf(-x)); }

__device__ __forceinline__ uint32_t smem_u32(const void* p) {
    uint32_t a;
    asm("{ .reg .u64 t; cvta.to.shared.u64 t, %1; cvt.u32.u64 %0, t; }" : "=r"(a) : "l"(p));
    return a;
}

#define LDSM4(r0, r1, r2, r3, a) \
    asm volatile("ldmatrix.sync.aligned.m8n8.x4.shared.b16 {%0,%1,%2,%3}, [%4];" \
                 : "=r"(r0), "=r"(r1), "=r"(r2), "=r"(r3) : "r"(a))
#define LDSM2(r0, r1, a) \
    asm volatile("ldmatrix.sync.aligned.m8n8.x2.shared.b16 {%0,%1}, [%2];" \
                 : "=r"(r0), "=r"(r1) : "r"(a))
#define MMA16816(c, a, b) \
    asm volatile("mma.sync.aligned.m16n8k16.row.col.f32.bf16.bf16.f32 " \
                 "{%0,%1,%2,%3}, {%4,%5,%6,%7}, {%8,%9}, {%0,%1,%2,%3};" \
                 : "+f"((c)[0]), "+f"((c)[1]), "+f"((c)[2]), "+f"((c)[3]) \
                 : "r"((a)[0]), "r"((a)[1]), "r"((a)[2]), "r"((a)[3]), "r"((b)[0]), "r"((b)[1]))
#define MMAI8(c, a, b) \
    asm volatile("mma.sync.aligned.m16n8k32.row.col.s32.s8.s8.s32 " \
                 "{%0,%1,%2,%3}, {%4,%5,%6,%7}, {%8,%9}, {%0,%1,%2,%3};" \
                 : "+r"((c)[0]), "+r"((c)[1]), "+r"((c)[2]), "+r"((c)[3]) \
                 : "r"((a)[0]), "r"((a)[1]), "r"((a)[2]), "r"((a)[3]), "r"((b)[0]), "r"((b)[1]))
#define MBAR_INIT(a, c)  asm volatile("mbarrier.init.shared.b64 [%0], %1;" :: "r"(a), "r"(c) : "memory")
#define MBAR_EXPECT(a, tx) asm volatile("mbarrier.arrive.expect_tx.shared.b64 _, [%0], %1;" :: "r"(a), "r"(tx) : "memory")
#define FENCE_ASYNC()    asm volatile("fence.proxy.async.shared::cta;" ::: "memory")
#define BULKCP(dst, src, sz, mb) \
    asm volatile("cp.async.bulk.shared::cluster.global.mbarrier::complete_tx::bytes [%0], [%1], %2, [%3];" \
                 :: "r"(dst), "l"(src), "r"(sz), "r"(mb) : "memory")

__device__ __forceinline__ void mbar_wait(uint32_t mb, uint32_t parity) {
    asm volatile(
        "{\n\t.reg .pred P;\n\t"
        "W%=:\n\t"
        "mbarrier.try_wait.parity.acquire.cta.shared::cta.b64 P, [%0], %1, 0x989680;\n\t"
        "@P bra.uni D%=;\n\t"
        "bra.uni W%=;\n\t"
        "D%=:\n\t}" :: "r"(mb), "r"(parity) : "memory");
}

// ---------------- setup ----------------
__global__ void k_setup(const void* __restrict__ cap_len_raw)
{
    __shared__ int len[BATCH];
    const int* p32 = (const int*)cap_len_raw;
    int is64 = (p32[1] == 0) ? 1 : 0;   // lengths in [2,32]; int64 high word == 0
    int i = threadIdx.x;
    if (i == 0) d_i64 = is64;
    if (i < BATCH) len[i] = p32[i << is64];
    __syncthreads();
    if (i < BATCH) {
        int li = len[i], r = 0;
        for (int j = 0; j < BATCH; j++) {
            int lj = len[j];
            if (lj > li || (lj == li && j < i)) r++;
        }
        d_sortind[r] = i;
        d_declen[r]  = li - 1;
    }
    __syncthreads();
    if (i < TDEC) {
        int c = 0;
        for (int b = 0; b < BATCH; b++)
            if (d_declen[b] > i) c++;
        d_cnt[i] = c;
    }
    __syncthreads();
    if (i == 0) {
        int acc = 0;
        for (int s = 0; s < TDEC; s++) { d_rowstart[s] = acc; acc += d_cnt[s]; }
        d_Mact = acc;
    }
    __syncthreads();
    for (int s = 0; s < TDEC; s++)
        if (i < d_cnt[s])
            d_rowout[d_rowstart[s] + i] = ((long long)i * TDEC + s) * VOCAB;
}

__global__ void k_tail(float* __restrict__ out, int out_size)
{
    int i = threadIdx.x;
    long long base = (long long)BATCH * TDEC * VOCAB;
    if (out_size >= (int)(base + 2 * BATCH) && i < BATCH) {
        out[base + i]         = (float)d_declen[i];
        out[base + BATCH + i] = (float)d_sortind[i];
    }
}

__global__ void k_packbias(const float* __restrict__ bih, const float* __restrict__ bhh)
{
    int p = blockIdx.x * 256 + threadIdx.x;
    int o = (p & 3) * 1024 + (p >> 2);
    d_biasPk[p] = bih[o] + bhh[o];
}

// ---------------- gather ----------------
__global__ void __launch_bounds__(256) k_gather(const float* __restrict__ enc,
                                                const void* __restrict__ caps_raw,
                                                const float* __restrict__ emb)
{
    int row = blockIdx.x;
    int t = row >> 6, b = row & 63;
    int sb = d_sortind[b];
    const float* src;
    if (t == 0) {
        src = enc + (long long)sb * EDIM;
    } else {
        int idx = sb * TCAP + (t - 1);
        int tok = ((const int*)caps_raw)[idx << d_i64];
        src = emb + (long long)tok * EDIM;
    }
    float4 v = ((const float4*)src)[threadIdx.x];
    __nv_bfloat16 hx = __float2bfloat16(v.x), hy = __float2bfloat16(v.y);
    __nv_bfloat16 hz = __float2bfloat16(v.z), hw = __float2bfloat16(v.w);
    __nv_bfloat162 hA; hA.x = hx; hA.y = hy;
    __nv_bfloat162 hB; hB.x = hz; hB.y = hw;
    __nv_bfloat162 lA, lB;
    lA.x = __float2bfloat16(v.x - __bfloat162float(hx));
    lA.y = __float2bfloat16(v.y - __bfloat162float(hy));
    lB.x = __float2bfloat16(v.z - __bfloat162float(hz));
    lB.y = __float2bfloat16(v.w - __bfloat162float(hw));
    int col = threadIdx.x * 4;
    int ch = col >> 6, kc = col & 63;
    size_t off = ((size_t)ch * MROWS + row) * CROW + kc * 2;
    *(__nv_bfloat162*)(d_XhiC + off)     = hA;
    *(__nv_bfloat162*)(d_XhiC + off + 4) = hB;
    *(__nv_bfloat162*)(d_XloC + off)     = lA;
    *(__nv_bfloat162*)(d_XloC + off + 4) = lB;
}

// ---------------- split weights (bf16 hi/lo, optional gate-pack perm) ----------------
__global__ void __launch_bounds__(256) k_split(const float4* __restrict__ src,
                                               char* __restrict__ hiC,
                                               char* __restrict__ loC, int nrows, int perm)
{
    int r = blockIdx.x;
    int p = perm ? ((r & 1023) * 4 + (r >> 10)) : r;
    int tid = threadIdx.x;
    float4 v = src[(size_t)r * 256 + tid];
    __nv_bfloat16 hx = __float2bfloat16(v.x), hy = __float2bfloat16(v.y);
    __nv_bfloat16 hz = __float2bfloat16(v.z), hw = __float2bfloat16(v.w);
    __nv_bfloat162 hA; hA.x = hx; hA.y = hy;
    __nv_bfloat162 hB; hB.x = hz; hB.y = hw;
    __nv_bfloat162 lA, lB;
    lA.x = __float2bfloat16(v.x - __bfloat162float(hx));
    lA.y = __float2bfloat16(v.y - __bfloat162float(hy));
    lB.x = __float2bfloat16(v.z - __bfloat162float(hz));
    lB.y = __float2bfloat16(v.w - __bfloat162float(hw));
    int col = tid * 4;
    int ch = col >> 6, kc = col & 63;
    size_t off = ((size_t)ch * nrows + p) * CROW + kc * 2;
    *(__nv_bfloat162*)(hiC + off)     = hA;
    *(__nv_bfloat162*)(hiC + off + 4) = hB;
    *(__nv_bfloat162*)(loC + off)     = lA;
    *(__nv_bfloat162*)(loC + off + 4) = lB;
}

// ---------------- quantize fc_W: per-row two-level int8 ----------------
__global__ void __launch_bounds__(256) k_quantW(const float4* __restrict__ W,
                                                char* __restrict__ P1C,
                                                char* __restrict__ P2C,
                                                float* __restrict__ wscale2)
{
    int n = blockIdx.x, tid = threadIdx.x;
    float4 v = W[(size_t)n * 256 + tid];
    float m = fmaxf(fmaxf(fabsf(v.x), fabsf(v.y)), fmaxf(fabsf(v.z), fabsf(v.w)));
#pragma unroll
    for (int o = 16; o; o >>= 1) m = fmaxf(m, __shfl_xor_sync(0xffffffffu, m, o));
    __shared__ float red[8];
    if ((tid & 31) == 0) red[tid >> 5] = m;
    __syncthreads();
    if (tid < 8) {
        float t = red[tid];
#pragma unroll
        for (int o = 4; o; o >>= 1) t = fmaxf(t, __shfl_xor_sync(0xffu, t, o));
        if (tid == 0) red[0] = t;
    }
    __syncthreads();
    float wmax = fmaxf(red[0], 1e-30f);
    float wn = wmax / 127.0f;
    float inv = 1.0f / wn;
    float vv[4] = { v.x, v.y, v.z, v.w };
    char q1[4], q2[4];
#pragma unroll
    for (int j = 0; j < 4; j++) {
        float q  = vv[j] * inv;
        float Q1 = rintf(q);
        float Q2 = rintf((q - Q1) * 128.0f);
        q1[j] = (char)(int)Q1;
        q2[j] = (char)(int)Q2;
    }
    int col = tid * 4, ch = col >> 7, kc = col & 127;
    size_t off = ((size_t)ch * VOCAB + n) * CROW + kc;
    *(char4*)(P1C + off) = make_char4(q1[0], q1[1], q1[2], q1[3]);
    *(char4*)(P2C + off) = make_char4(q2[0], q2[1], q2[2], q2[3]);
    if (tid == 0) wscale2[n] = wn / 127.0f;
}

// ================= bf16 bulk-copy mma.sync GEMM (256x128) — input gates =================
#define A_ST   (256 * CROW)
#define B_ST   (128 * CROW)
#define STG2   (2 * A_ST + 2 * B_ST)
#define SMEMB  (128 + 2 * STG2)

__global__ void __launch_bounds__(256, 1) k_mma(
    const char* __restrict__ AhiC, const char* __restrict__ AloC,
    const char* __restrict__ BhiC, const char* __restrict__ BloC,
    int arows, int brows,
    const float* __restrict__ bias1,
    float* __restrict__ outp,
    const int* __restrict__ pMact)
{
    extern __shared__ char smem[];
    int tid = threadIdx.x;
    int m0 = blockIdx.x * 256;
    int n0 = blockIdx.y * 128;
    int Mact = *pMact;
    if (m0 >= Mact) return;

    uint32_t sb  = smem_u32(smem);
    uint32_t stg = sb + 128;
    int wid = tid >> 5, lane = tid & 31;
    int wm = wid >> 1, wn = wid & 1;      // warp tile 64x64

    if (tid == 0) { MBAR_INIT(sb + 0, 1); MBAR_INIT(sb + 8, 1); }
    FENCE_ASYNC();
    __syncthreads();

    auto issue = [&](int c, int slot) {
        uint32_t mb = sb + slot * 8;
        MBAR_EXPECT(mb, STG2);
        uint32_t base = stg + slot * STG2;
        BULKCP(base,                AhiC + ((size_t)c * arows + m0) * CROW, A_ST, mb);
        BULKCP(base + A_ST,         AloC + ((size_t)c * arows + m0) * CROW, A_ST, mb);
        BULKCP(base + 2 * A_ST,         BhiC + ((size_t)c * brows + n0) * CROW, B_ST, mb);
        BULKCP(base + 2 * A_ST + B_ST,  BloC + ((size_t)c * brows + n0) * CROW, B_ST, mb);
    };

    float acc[4][8][4];
#pragma unroll
    for (int a = 0; a < 4; a++)
#pragma unroll
        for (int b = 0; b < 8; b++)
#pragma unroll
            for (int q = 0; q < 4; q++) acc[a][b][q] = 0.f;

    if (tid == 0) { issue(0, 0); issue(1, 1); }
    int ph[2] = { 0, 0 };

    for (int c = 0; c < NCHUNK; c++) {
        int st = c & 1;
        mbar_wait(sb + st * 8, ph[st]); ph[st] ^= 1;
        uint32_t sbuf = stg + st * STG2;

#pragma unroll
        for (int kk = 0; kk < 4; kk++) {
            uint32_t ah[4][4], al[4][4], bh[4][4], bl[4][4];
            uint32_t abase = sbuf + (wm * 64 + (lane & 15)) * CROW + ((lane >> 4) & 1) * 16 + kk * 32;
#pragma unroll
            for (int mi = 0; mi < 4; mi++)
                LDSM4(ah[mi][0], ah[mi][1], ah[mi][2], ah[mi][3], abase + mi * 16 * CROW);
            uint32_t bbase = sbuf + 2 * A_ST +
                             (wn * 64 + (lane & 7) + ((lane >> 4) & 1) * 8) * CROW +
                             ((lane >> 3) & 1) * 16 + kk * 32;
#pragma unroll
            for (int nj = 0; nj < 4; nj++)
                LDSM4(bh[nj][0], bh[nj][1], bh[nj][2], bh[nj][3], bbase + nj * 16 * CROW);
#pragma unroll
            for (int nj = 0; nj < 4; nj++)
                LDSM4(bl[nj][0], bl[nj][1], bl[nj][2], bl[nj][3], bbase + B_ST + nj * 16 * CROW);
#pragma unroll
            for (int mi = 0; mi < 4; mi++)
#pragma unroll
                for (int nj = 0; nj < 4; nj++) {
                    MMA16816(acc[mi][2 * nj],     ah[mi], &bh[nj][0]);
                    MMA16816(acc[mi][2 * nj + 1], ah[mi], &bh[nj][2]);
                    MMA16816(acc[mi][2 * nj],     ah[mi], &bl[nj][0]);
                    MMA16816(acc[mi][2 * nj + 1], ah[mi], &bl[nj][2]);
                }
#pragma unroll
            for (int mi = 0; mi < 4; mi++)
                LDSM4(al[mi][0], al[mi][1], al[mi][2], al[mi][3], abase + A_ST + mi * 16 * CROW);
#pragma unroll
            for (int mi = 0; mi < 4; mi++)
#pragma unroll
                for (int nj = 0; nj < 4; nj++) {
                    MMA16816(acc[mi][2 * nj],     al[mi], &bh[nj][0]);
                    MMA16816(acc[mi][2 * nj + 1], al[mi], &bh[nj][2]);
                }
        }
        __syncthreads();
        if (tid == 0 && c + 2 < NCHUNK) issue(c + 2, st);
    }
    __syncthreads();

    // stage C through smem (256 x 132) for coalesced writeout
    float* Cst = (float*)smem;
#pragma unroll
    for (int mi = 0; mi < 4; mi++)
#pragma unroll
        for (int nj = 0; nj < 4; nj++)
#pragma unroll
            for (int q = 0; q < 2; q++) {
                int ni = 2 * nj + q;
                int r = wm * 64 + mi * 16 + (lane >> 2);
                int cb = wn * 64 + nj * 16 + q * 8 + (lane & 3) * 2;
                Cst[r * 132 + cb]           = acc[mi][ni][0];
                Cst[r * 132 + cb + 1]       = acc[mi][ni][1];
                Cst[(r + 8) * 132 + cb]     = acc[mi][ni][2];
                Cst[(r + 8) * 132 + cb + 1] = acc[mi][ni][3];
            }
    __syncthreads();

    for (int it = tid; it < 256 * 32; it += 256) {
        int row = it >> 5;
        int col = (it & 31) * 4;
        int m = m0 + row;
        float4 v = *(float4*)&Cst[row * 132 + col];
        float4 b1 = *(const float4*)(bias1 + n0 + col);
        v.x += b1.x; v.y += b1.y; v.z += b1.z; v.w += b1.w;
        *(float4*)(outp + (size_t)m * NG + n0 + col) = v;
    }
}

// ================= int8 two-level fc GEMM (block 256x64, warp 64x32) =================
#define A_STI  (256 * CROW)              // 36864
#define B_STI  (64 * CROW)               // 9216
#define STGI   (2 * A_STI + 2 * B_STI)   // 92160
#define SMEMI  (128 + 2 * STGI)          // 184448

__global__ void __launch_bounds__(256, 1) k_mma_i8(
    const char* __restrict__ AP1, const char* __restrict__ AP2,
    const char* __restrict__ BQ1, const char* __restrict__ BQ2,
    const float* __restrict__ wscale2, const float* __restrict__ fcb,
    float* __restrict__ outp, const long long* __restrict__ rowout,
    const int* __restrict__ pMact)
{
    extern __shared__ char smem[];
    int tid = threadIdx.x;
    int m0 = blockIdx.x * 256;
    int n0 = blockIdx.y * 64;
    int Mact = *pMact;
    if (m0 >= Mact) return;

    uint32_t sb  = smem_u32(smem);
    uint32_t stg = sb + 128;
    int wid = tid >> 5, lane = tid & 31;
    int wm = wid >> 1, wn = wid & 1;      // warp tile 64x32

    if (tid == 0) { MBAR_INIT(sb + 0, 1); MBAR_INIT(sb + 8, 1); }
    FENCE_ASYNC();
    __syncthreads();

    auto issue = [&](int c, int slot) {
        uint32_t mb = sb + slot * 8;
        MBAR_EXPECT(mb, STGI);
        uint32_t base = stg + slot * STGI;
        BULKCP(base,                     AP1 + ((size_t)c * MROWS + m0) * CROW, A_STI, mb);
        BULKCP(base + A_STI,             AP2 + ((size_t)c * MROWS + m0) * CROW, A_STI, mb);
        BULKCP(base + 2 * A_STI,         BQ1 + ((size_t)c * VOCAB + n0) * CROW, B_STI, mb);
        BULKCP(base + 2 * A_STI + B_STI, BQ2 + ((size_t)c * VOCAB + n0) * CROW, B_STI, mb);
    };

    int acc1[4][4][4], acc2[4][4][4];
#pragma unroll
    for (int a = 0; a < 4; a++)
#pragma unroll
        for (int b = 0; b < 4; b++)
#pragma unroll
            for (int q = 0; q < 4; q++) { acc1[a][b][q] = 0; acc2[a][b][q] = 0; }

    if (tid == 0) { issue(0, 0); issue(1, 1); }
    int ph[2] = { 0, 0 };

    for (int c = 0; c < NCH8; c++) {
        int st = c & 1;
        mbar_wait(sb + st * 8, ph[st]); ph[st] ^= 1;
        uint32_t sbuf = stg + st * STGI;

#pragma unroll
        for (int kk = 0; kk < 4; kk++) {      // 4 x k32 per 128-int8 chunk
            uint32_t a1[4][4], a2[4][4], b1[4][2], b2[4][2];
            uint32_t abase = sbuf + (wm * 64 + (lane & 15)) * CROW + ((lane >> 4) & 1) * 16 + kk * 32;
#pragma unroll
            for (int mi = 0; mi < 4; mi++)
                LDSM4(a1[mi][0], a1[mi][1], a1[mi][2], a1[mi][3], abase + mi * 16 * CROW);
#pragma unroll
            for (int mi = 0; mi < 4; mi++)
                LDSM4(a2[mi][0], a2[mi][1], a2[mi][2], a2[mi][3], abase + A_STI + mi * 16 * CROW);
            uint32_t bbase = sbuf + 2 * A_STI + (wn * 32 + (lane & 7)) * CROW +
                             ((lane >> 3) & 1) * 16 + kk * 32;
#pragma unroll
            for (int ni = 0; ni < 4; ni++)
                LDSM2(b1[ni][0], b1[ni][1], bbase + ni * 8 * CROW);
#pragma unroll
            for (int ni = 0; ni < 4; ni++)
                LDSM2(b2[ni][0], b2[ni][1], bbase + B_STI + ni * 8 * CROW);
#pragma unroll
            for (int mi = 0; mi < 4; mi++)
#pragma unroll
                for (int ni = 0; ni < 4; ni++) {
                    MMAI8(acc1[mi][ni], a1[mi], b1[ni]);   // S11
                    MMAI8(acc2[mi][ni], a1[mi], b2[ni]);   // S12 (scale 1/128)
                    MMAI8(acc2[mi][ni], a2[mi], b1[ni]);   // S21 (scale 1/128)
                }
        }
        __syncthreads();
        if (tid == 0 && c + 2 < NCH8) issue(c + 2, st);
    }
    __syncthreads();

    // stage combined float C through smem: 256 x 68
    float* Cst = (float*)smem;
#pragma unroll
    for (int mi = 0; mi < 4; mi++)
#pragma unroll
        for (int ni = 0; ni < 4; ni++) {
            int r  = wm * 64 + mi * 16 + (lane >> 2);
            int cb = wn * 32 + ni * 8 + (lane & 3) * 2;
            Cst[r * 68 + cb]           = (float)acc1[mi][ni][0] + (float)acc2[mi][ni][0] * 0.0078125f;
            Cst[r * 68 + cb + 1]       = (float)acc1[mi][ni][1] + (float)acc2[mi][ni][1] * 0.0078125f;
            Cst[(r + 8) * 68 + cb]     = (float)acc1[mi][ni][2] + (float)acc2[mi][ni][2] * 0.0078125f;
            Cst[(r + 8) * 68 + cb + 1] = (float)acc1[mi][ni][3] + (float)acc2[mi][ni][3] * 0.0078125f;
        }
    __syncthreads();

    for (int it = tid; it < 256 * 16; it += 256) {
        int row = it >> 4;
        int col = (it & 15) * 4;
        int m = m0 + row;
        if (m >= Mact) continue;
        float4 v  = *(float4*)&Cst[row * 68 + col];
        float4 ws = *(const float4*)(wscale2 + n0 + col);
        float4 bb = *(const float4*)(fcb + n0 + col);
        v.x = v.x * ws.x + bb.x;
        v.y = v.y * ws.y + bb.y;
        v.z = v.z * ws.z + bb.z;
        v.w = v.w * ws.w + bb.w;
        *(float4*)(outp + rowout[m] + n0 + col) = v;
    }
}

// ---------------- step 0 ----------------
__global__ void __launch_bounds__(256) k_step0()
{
    int b = blockIdx.x;
    for (int d = threadIdx.x; d < DDIM; d += 256) {
        float4 gx = *(const float4*)&d_gatesx[(size_t)b * NG + d * 4];
        float c = sigmf(gx.x) * tanhf(gx.z);
        float h = sigmf(gx.w) * tanhf(c);
        d_c[b * DDIM + d] = c;
        __nv_bfloat16 hh = __float2bfloat16(h);
        __nv_bfloat16 hl = __float2bfloat16(h - __bfloat162float(hh));
        int ch = d >> 6, kc = d & 63;
        size_t o = ((size_t)ch * BATCH + b) * CROW + kc * 2;
        *(__nv_bfloat16*)(d_HpHi[0] + o) = hh;
        *(__nv_bfloat16*)(d_HpLo[0] + o) = hl;
    }
}

// ---------------- fused recurrent step ----------------
#define SOPA 9216
#define SOPB 18432
#define SSTG (2 * SOPA + 2 * SOPB)
#define SMEM_S (128 + 2 * SSTG)

__global__ void __launch_bounds__(256, 1) k_stepf(int s)
{
    extern __shared__ char smem[];
    int tid = threadIdx.x;
    int nt = blockIdx.x, ks = blockIdx.y;
    int n0 = nt * 128;
    int rp = (s - 1) & 1, wp = s & 1;

    uint32_t sb  = smem_u32(smem);
    uint32_t stg = sb + 128;
    int wid = tid >> 5, lane = tid & 31;
    int wm = wid & 1, wn = wid >> 1;

    if (tid == 0) { MBAR_INIT(sb + 0, 1); MBAR_INIT(sb + 8, 1); }
    FENCE_ASYNC();
    __syncthreads();

    auto issue = [&](int cc, int slot) {
        uint32_t mb = sb + slot * 8;
        int cg = ks * 4 + cc;
        MBAR_EXPECT(mb, SSTG);
        uint32_t base = stg + slot * SSTG;
        BULKCP(base,                   d_HpHi[rp] + (size_t)cg * SOPA, SOPA, mb);
        BULKCP(base + SOPA,            d_HpLo[rp] + (size_t)cg * SOPA, SOPA, mb);
        BULKCP(base + 2 * SOPA,        d_WhhHiC + ((size_t)cg * NG + n0) * CROW, SOPB, mb);
        BULKCP(base + 2 * SOPA + SOPB, d_WhhLoC + ((size_t)cg * NG + n0) * CROW, SOPB, mb);
    };

    float acc[2][4][4];
#pragma unroll
    for (int a = 0; a < 2; a++)
#pragma unroll
        for (int b = 0; b < 4; b++)
#pragma unroll
            for (int q = 0; q < 4; q++) acc[a][b][q] = 0.f;

    if (tid == 0) { issue(0, 0); issue(1, 1); }
    int ph[2] = { 0, 0 };

    for (int c = 0; c < 4; c++) {
        int st = c & 1;
        mbar_wait(sb + st * 8, ph[st]); ph[st] ^= 1;
        uint32_t sbuf = stg + st * SSTG;
#pragma unroll
        for (int kk = 0; kk < 4; kk++) {
            uint32_t ah[2][4], al[2][4], bh[4][2], bl[4][2];
            uint32_t abase = sbuf + (wm * 32 + (lane & 15)) * CROW + (lane >> 4) * 16 + kk * 32;
#pragma unroll
            for (int mi = 0; mi < 2; mi++)
                LDSM4(ah[mi][0], ah[mi][1], ah[mi][2], ah[mi][3], abase + mi * 16 * CROW);
#pragma unroll
            for (int mi = 0; mi < 2; mi++)
                LDSM4(al[mi][0], al[mi][1], al[mi][2], al[mi][3], abase + SOPA + mi * 16 * CROW);
            uint32_t bbase = sbuf + 2 * SOPA + (wn * 32 + (lane & 7)) * CROW + ((lane >> 3) & 1) * 16 + kk * 32;
#pragma unroll
            for (int ni = 0; ni < 4; ni++)
                LDSM2(bh[ni][0], bh[ni][1], bbase + ni * 8 * CROW);
#pragma unroll
            for (int ni = 0; ni < 4; ni++)
                LDSM2(bl[ni][0], bl[ni][1], bbase + SOPB + ni * 8 * CROW);
#pragma unroll
            for (int mi = 0; mi < 2; mi++)
#pragma unroll
                for (int ni = 0; ni < 4; ni++) {
                    MMA16816(acc[mi][ni], ah[mi], bh[ni]);
                    MMA16816(acc[mi][ni], al[mi], bh[ni]);
                    MMA16816(acc[mi][ni], ah[mi], bl[ni]);
                }
        }
        __syncthreads();
        if (tid == 0 && c + 2 < 4) issue(c + 2, st);
    }

#pragma unroll
    for (int mi = 0; mi < 2; mi++)
#pragma unroll
        for (int ni = 0; ni < 4; ni++) {
            int r = wm * 32 + mi * 16 + (lane >> 2);
            int col = n0 + wn * 32 + ni * 8 + (lane & 3) * 2;
            *(float2*)&d_part[ks][r][col]     = make_float2(acc[mi][ni][0], acc[mi][ni][1]);
            *(float2*)&d_part[ks][r + 8][col] = make_float2(acc[mi][ni][2], acc[mi][ni][3]);
        }
    __threadfence();
    __syncthreads();

    __shared__ int s_old;
    if (tid == 0) s_old = atomicAdd(&d_ncnt[nt], 1);
    __syncthreads();
    if (s_old != KSPLIT - 1) return;
    __threadfence();

    int cnt = d_cnt[s - 1];
    int rs  = d_rowstart[s - 1];
    int nd0 = n0 >> 2;
    for (int it = tid; it < BATCH * 32; it += 256) {
        int b = it >> 5, di = it & 31;
        int dim = nd0 + di;
        int ch = dim >> 6, kc = dim & 63;
        size_t hoff = ((size_t)ch * BATCH + b) * CROW + kc * 2;
        if (b < cnt) {
            float4 g = *(const float4*)&d_gatesx[((size_t)s * BATCH + b) * NG + dim * 4];
            float4 p0 = *(const float4*)&d_part[0][b][dim * 4];
            float4 p1 = *(const float4*)&d_part[1][b][dim * 4];
            float4 p2 = *(const float4*)&d_part[2][b][dim * 4];
            float4 p3 = *(const float4*)&d_part[3][b][dim * 4];
            float gi = g.x + p0.x + p1.x + p2.x + p3.x;
            float gf = g.y + p0.y + p1.y + p2.y + p3.y;
            float gg = g.z + p0.z + p1.z + p2.z + p3.z;
            float go = g.w + p0.w + p1.w + p2.w + p3.w;
            float cold = d_c[b * DDIM + dim];
            float cn = sigmf(gf) * cold + sigmf(gi) * tanhf(gg);
            float hn = sigmf(go) * tanhf(cn);
            d_c[b * DDIM + dim] = cn;
            __nv_bfloat16 hh = __float2bfloat16(hn);
            __nv_bfloat16 hl = __float2bfloat16(hn - __bfloat162float(hh));
            *(__nv_bfloat16*)(d_HpHi[wp] + hoff) = hh;
            *(__nv_bfloat16*)(d_HpLo[wp] + hoff) = hl;
            // int8 two-level for fc: h in [-1,1], scale 1/127
            float u  = hn * 127.0f;
            float q1 = rintf(u);
            float q2 = rintf((u - q1) * 128.0f);
            int ch8 = dim >> 7, kc8 = dim & 127;
            size_t co = ((size_t)ch8 * MROWS + rs + b) * CROW + kc8;
            d_HP1C[co] = (char)(int)q1;
            d_HP2C[co] = (char)(int)q2;
        } else {
            *(__nv_bfloat16*)(d_HpHi[wp] + hoff) = *(const __nv_bfloat16*)(d_HpHi[rp] + hoff);
            *(__nv_bfloat16*)(d_HpLo[wp] + hoff) = *(const __nv_bfloat16*)(d_HpLo[rp] + hoff);
        }
    }
    if (tid == 0) d_ncnt[nt] = 0;
}

// ---------------- launch ----------------
extern "C" void kernel_launch(void* const* d_in, const int* in_sizes, int n_in,
                              void* d_out, int out_size)
{
    const float* enc  = (const float*)d_in[0];
    const void*  caps = d_in[1];
    const void*  clen = d_in[2];
    const float* emb  = (const float*)d_in[3];
    const float* Wih  = (const float*)d_in[4];
    const float* Whh  = (const float*)d_in[5];
    const float* bih  = (const float*)d_in[6];
    const float* bhh  = (const float*)d_in[7];
    const float* fcW  = (const float*)d_in[8];
    const float* fcb  = (const float*)d_in[9];
    float* out = (float*)d_out;

    static cudaStream_t s2 = nullptr;
    static cudaEvent_t ev0 = nullptr, ev1 = nullptr;
    if (!s2) {
        cudaFuncSetAttribute(k_mma,    cudaFuncAttributeMaxDynamicSharedMemorySize, SMEMB);
        cudaFuncSetAttribute(k_mma_i8, cudaFuncAttributeMaxDynamicSharedMemorySize, SMEMI);
        cudaFuncSetAttribute(k_stepf,  cudaFuncAttributeMaxDynamicSharedMemorySize, SMEM_S);
        cudaStreamCreateWithFlags(&s2, cudaStreamNonBlocking);
        cudaEventCreateWithFlags(&ev0, cudaEventDisableTiming);
        cudaEventCreateWithFlags(&ev1, cudaEventDisableTiming);
    }

    char *pXhiC, *pXloC, *pWihHiC, *pWihLoC, *pWhhHiC, *pWhhLoC;
    char *pHP1C, *pHP2C, *pWfcP1C, *pWfcP2C;
    float *pGatesx, *pBiasPk, *pWscale;
    long long* pRowout;
    int *pMact, *pM2048;
    cudaGetSymbolAddress((void**)&pXhiC, d_XhiC);
    cudaGetSymbolAddress((void**)&pXloC, d_XloC);
    cudaGetSymbolAddress((void**)&pWihHiC, d_WihHiC);
    cudaGetSymbolAddress((void**)&pWihLoC, d_WihLoC);
    cudaGetSymbolAddress((void**)&pWhhHiC, d_WhhHiC);
    cudaGetSymbolAddress((void**)&pWhhLoC, d_WhhLoC);
    cudaGetSymbolAddress((void**)&pHP1C, d_HP1C);
    cudaGetSymbolAddress((void**)&pHP2C, d_HP2C);
    cudaGetSymbolAddress((void**)&pWfcP1C, d_WfcP1C);
    cudaGetSymbolAddress((void**)&pWfcP2C, d_WfcP2C);
    cudaGetSymbolAddress((void**)&pGatesx, d_gatesx);
    cudaGetSymbolAddress((void**)&pBiasPk, d_biasPk);
    cudaGetSymbolAddress((void**)&pWscale, d_wscale);
    cudaGetSymbolAddress((void**)&pRowout, d_rowout);
    cudaGetSymbolAddress((void**)&pMact, d_Mact);
    cudaGetSymbolAddress((void**)&pM2048, d_M2048);

    // side stream: output memset + fc weight quantization, overlapped
    cudaEventRecord(ev0, 0);
    cudaStreamWaitEvent(s2, ev0, 0);
    cudaMemsetAsync(out, 0, (size_t)out_size * sizeof(float), s2);
    k_quantW<<<VOCAB, 256, 0, s2>>>((const float4*)fcW, pWfcP1C, pWfcP2C, pWscale);
    cudaEventRecord(ev1, s2);

    // main stream
    cudaMemsetAsync(pHP1C, 0, (size_t)NCH8 * MROWS * CROW);
    cudaMemsetAsync(pHP2C, 0, (size_t)NCH8 * MROWS * CROW);
    k_setup<<<1, 64>>>(clen);
    k_gather<<<TCAP * BATCH, 256>>>(enc, caps, emb);
    k_split<<<NG, 256>>>((const float4*)Wih, pWihHiC, pWihLoC, NG, 1);
    k_split<<<NG, 256>>>((const float4*)Whh, pWhhHiC, pWhhLoC, NG, 1);
    k_packbias<<<NG / 256, 256>>>(bih, bhh);

    // gates_x = X @ WihPk^T + biasPk   (M=2048, N=4096 packed)
    k_mma<<<dim3(8, 32), 256, SMEMB>>>(pXhiC, pXloC, pWihHiC, pWihLoC,
                                       MROWS, NG, pBiasPk, pGatesx, pM2048);

    k_step0<<<BATCH, 256>>>();
    for (int s = 1; s <= TDEC; s++)
        k_stepf<<<dim3(NTILES, KSPLIT), 256, SMEM_S>>>(s);

    cudaStreamWaitEvent(0, ev1, 0);
    k_tail<<<1, 64>>>(out, out_size);

    // predictions = Hq @ WfcQ^T (int8 two-level), scaled + bias, scattered
    k_mma_i8<<<dim3(8, 500), 256, SMEMI>>>(pHP1C, pHP2C, pWfcP1C, pWfcP2C,
                                           pWscale, fcb, out, pRowout, pMact);
}

// round 12
// speedup vs baseline: 1.9244x; 1.9244x over previous
#include <cuda_runtime.h>
#include <cuda_bf16.h>
#include <cstdint>

#define BATCH 64
#define TCAP  32
#define VOCAB 32000
#define EDIM  1024
#define DDIM  1024
#define TDEC  31
#define NG    4096
#define MROWS 2048
#define CROW  144
#define NCHUNK 16
#define KSPLIT 4
#define NTILES 32          // 4096 / 128

// ---------------- static scratch ----------------
__device__ int   d_sortind[BATCH];
__device__ int   d_declen[BATCH];
__device__ int   d_cnt[TDEC];
__device__ int   d_rowstart[TDEC];
__device__ int   d_Mact;
__device__ int   d_M2048 = 2048;
__device__ int   d_i64;
__device__ int   d_ncnt[NTILES];
__device__ long long d_rowout[MROWS];
__device__ __align__(16) float d_gatesx[TCAP * BATCH * NG];   // gate-PACKED cols
__device__ __align__(16) float d_biasPk[NG];
__device__ __align__(16) float d_c[BATCH * DDIM];
__device__ __align__(16) float d_part[KSPLIT][BATCH][NG];
// chunked + padded bf16 operands: [chunk][row][144B]
__device__ __align__(16) char d_XhiC [NCHUNK * MROWS * CROW];
__device__ __align__(16) char d_XloC [NCHUNK * MROWS * CROW];
__device__ __align__(16) char d_HchiC[NCHUNK * MROWS * CROW];
__device__ __align__(16) char d_HcloC[NCHUNK * MROWS * CROW];
__device__ __align__(16) char d_WihHiC[NCHUNK * NG * CROW];   // gate-packed rows
__device__ __align__(16) char d_WihLoC[NCHUNK * NG * CROW];
__device__ __align__(16) char d_WhhHiC[NCHUNK * NG * CROW];
__device__ __align__(16) char d_WhhLoC[NCHUNK * NG * CROW];
__device__ __align__(16) char d_WfcHiC[NCHUNK * VOCAB * CROW];
__device__ __align__(16) char d_WfcLoC[NCHUNK * VOCAB * CROW];
__device__ __align__(16) char d_HpHi[2][NCHUNK * BATCH * CROW];
__device__ __align__(16) char d_HpLo[2][NCHUNK * BATCH * CROW];

__device__ __forceinline__ float sigmf(float x) { return 1.0f / (1.0f + expf(-x)); }

__device__ __forceinline__ uint32_t smem_u32(const void* p) {
    uint32_t a;
    asm("{ .reg .u64 t; cvta.to.shared.u64 t, %1; cvt.u32.u64 %0, t; }" : "=r"(a) : "l"(p));
    return a;
}

#define LDSM4(r0, r1, r2, r3, a) \
    asm volatile("ldmatrix.sync.aligned.m8n8.x4.shared.b16 {%0,%1,%2,%3}, [%4];" \
                 : "=r"(r0), "=r"(r1), "=r"(r2), "=r"(r3) : "r"(a))
#define LDSM2(r0, r1, a) \
    asm volatile("ldmatrix.sync.aligned.m8n8.x2.shared.b16 {%0,%1}, [%2];" \
                 : "=r"(r0), "=r"(r1) : "r"(a))
#define MMA16816(c, a, b) \
    asm volatile("mma.sync.aligned.m16n8k16.row.col.f32.bf16.bf16.f32 " \
                 "{%0,%1,%2,%3}, {%4,%5,%6,%7}, {%8,%9}, {%0,%1,%2,%3};" \
                 : "+f"((c)[0]), "+f"((c)[1]), "+f"((c)[2]), "+f"((c)[3]) \
                 : "r"((a)[0]), "r"((a)[1]), "r"((a)[2]), "r"((a)[3]), "r"((b)[0]), "r"((b)[1]))
#define MBAR_INIT(a, c)  asm volatile("mbarrier.init.shared.b64 [%0], %1;" :: "r"(a), "r"(c) : "memory")
#define MBAR_EXPECT(a, tx) asm volatile("mbarrier.arrive.expect_tx.shared.b64 _, [%0], %1;" :: "r"(a), "r"(tx) : "memory")
#define FENCE_ASYNC()    asm volatile("fence.proxy.async.shared::cta;" ::: "memory")
#define BULKCP(dst, src, sz, mb) \
    asm volatile("cp.async.bulk.shared::cluster.global.mbarrier::complete_tx::bytes [%0], [%1], %2, [%3];" \
                 :: "r"(dst), "l"(src), "r"(sz), "r"(mb) : "memory")

__device__ __forceinline__ void mbar_wait(uint32_t mb, uint32_t parity) {
    asm volatile(
        "{\n\t.reg .pred P;\n\t"
        "W%=:\n\t"
        "mbarrier.try_wait.parity.acquire.cta.shared::cta.b64 P, [%0], %1, 0x989680;\n\t"
        "@P bra.uni D%=;\n\t"
        "bra.uni W%=;\n\t"
        "D%=:\n\t}" :: "r"(mb), "r"(parity) : "memory");
}

// ---------------- setup ----------------
__global__ void k_setup(const void* __restrict__ cap_len_raw)
{
    __shared__ int len[BATCH];
    const int* p32 = (const int*)cap_len_raw;
    int is64 = (p32[1] == 0) ? 1 : 0;   // lengths in [2,32]; int64 high word == 0
    int i = threadIdx.x;
    if (i == 0) d_i64 = is64;
    if (i < BATCH) len[i] = p32[i << is64];
    __syncthreads();
    if (i < BATCH) {
        int li = len[i], r = 0;
        for (int j = 0; j < BATCH; j++) {
            int lj = len[j];
            if (lj > li || (lj == li && j < i)) r++;
        }
        d_sortind[r] = i;
        d_declen[r]  = li - 1;
    }
    __syncthreads();
    if (i < TDEC) {
        int c = 0;
        for (int b = 0; b < BATCH; b++)
            if (d_declen[b] > i) c++;
        d_cnt[i] = c;
    }
    __syncthreads();
    if (i == 0) {
        int acc = 0;
        for (int s = 0; s < TDEC; s++) { d_rowstart[s] = acc; acc += d_cnt[s]; }
        d_Mact = acc;
    }
    __syncthreads();
    for (int s = 0; s < TDEC; s++)
        if (i < d_cnt[s])
            d_rowout[d_rowstart[s] + i] = ((long long)i * TDEC + s) * VOCAB;
}

__global__ void k_tail(float* __restrict__ out, int out_size)
{
    int i = threadIdx.x;
    long long base = (long long)BATCH * TDEC * VOCAB;
    if (out_size >= (int)(base + 2 * BATCH) && i < BATCH) {
        out[base + i]         = (float)d_declen[i];
        out[base + BATCH + i] = (float)d_sortind[i];
    }
}

__global__ void k_packbias(const float* __restrict__ bih, const float* __restrict__ bhh)
{
    int p = blockIdx.x * 256 + threadIdx.x;
    int o = (p & 3) * 1024 + (p >> 2);
    d_biasPk[p] = bih[o] + bhh[o];
}

// ---------------- gather ----------------
__global__ void __launch_bounds__(256) k_gather(const float* __restrict__ enc,
                                                const void* __restrict__ caps_raw,
                                                const float* __restrict__ emb)
{
    int row = blockIdx.x;
    int t = row >> 6, b = row & 63;
    int sb = d_sortind[b];
    const float* src;
    if (t == 0) {
        src = enc + (long long)sb * EDIM;
    } else {
        int idx = sb * TCAP + (t - 1);
        int tok = ((const int*)caps_raw)[idx << d_i64];
        src = emb + (long long)tok * EDIM;
    }
    float4 v = ((const float4*)src)[threadIdx.x];
    __nv_bfloat16 hx = __float2bfloat16(v.x), hy = __float2bfloat16(v.y);
    __nv_bfloat16 hz = __float2bfloat16(v.z), hw = __float2bfloat16(v.w);
    __nv_bfloat162 hA; hA.x = hx; hA.y = hy;
    __nv_bfloat162 hB; hB.x = hz; hB.y = hw;
    __nv_bfloat162 lA, lB;
    lA.x = __float2bfloat16(v.x - __bfloat162float(hx));
    lA.y = __float2bfloat16(v.y - __bfloat162float(hy));
    lB.x = __float2bfloat16(v.z - __bfloat162float(hz));
    lB.y = __float2bfloat16(v.w - __bfloat162float(hw));
    int col = threadIdx.x * 4;
    int ch = col >> 6, kc = col & 63;
    size_t off = ((size_t)ch * MROWS + row) * CROW + kc * 2;
    *(__nv_bfloat162*)(d_XhiC + off)     = hA;
    *(__nv_bfloat162*)(d_XhiC + off + 4) = hB;
    *(__nv_bfloat162*)(d_XloC + off)     = lA;
    *(__nv_bfloat162*)(d_XloC + off + 4) = lB;
}

// ---------------- split weights ----------------
__global__ void __launch_bounds__(256) k_split(const float4* __restrict__ src,
                                               char* __restrict__ hiC,
                                               char* __restrict__ loC, int nrows, int perm)
{
    int r = blockIdx.x;
    int p = perm ? ((r & 1023) * 4 + (r >> 10)) : r;
    int tid = threadIdx.x;
    float4 v = src[(size_t)r * 256 + tid];
    __nv_bfloat16 hx = __float2bfloat16(v.x), hy = __float2bfloat16(v.y);
    __nv_bfloat16 hz = __float2bfloat16(v.z), hw = __float2bfloat16(v.w);
    __nv_bfloat162 hA; hA.x = hx; hA.y = hy;
    __nv_bfloat162 hB; hB.x = hz; hB.y = hw;
    __nv_bfloat162 lA, lB;
    lA.x = __float2bfloat16(v.x - __bfloat162float(hx));
    lA.y = __float2bfloat16(v.y - __bfloat162float(hy));
    lB.x = __float2bfloat16(v.z - __bfloat162float(hz));
    lB.y = __float2bfloat16(v.w - __bfloat162float(hw));
    int col = tid * 4;
    int ch = col >> 6, kc = col & 63;
    size_t off = ((size_t)ch * nrows + p) * CROW + kc * 2;
    *(__nv_bfloat162*)(hiC + off)     = hA;
    *(__nv_bfloat162*)(hiC + off + 4) = hB;
    *(__nv_bfloat162*)(loC + off)     = lA;
    *(__nv_bfloat162*)(loC + off + 4) = lB;
}

// ================= bulk-copy mma.sync GEMM (256x128, warp tile 64x64) =================
#define A_ST   (256 * CROW)          // 36864 per A operand per stage
#define B_ST   (128 * CROW)          // 18432 per B operand per stage
#define STG2   (2 * A_ST + 2 * B_ST) // 110592 per stage
#define SMEMB  (128 + 2 * STG2)      // 221312

__global__ void __launch_bounds__(256, 1) k_mma(
    const char* __restrict__ AhiC, const char* __restrict__ AloC,
    const char* __restrict__ BhiC, const char* __restrict__ BloC,
    int arows, int brows,
    const float* __restrict__ bias1,
    float* __restrict__ outp, const long long* __restrict__ rowout,
    const int* __restrict__ pMact, int mode)
{
    extern __shared__ char smem[];
    int tid = threadIdx.x;
    int m0 = blockIdx.x * 256;
    int n0 = blockIdx.y * 128;
    int Mact = *pMact;
    if (m0 >= Mact) return;

    uint32_t sb  = smem_u32(smem);
    uint32_t stg = sb + 128;
    int wid = tid >> 5, lane = tid & 31;
    int wm = wid >> 1, wn = wid & 1;      // warp tile 64x64

    if (tid == 0) { MBAR_INIT(sb + 0, 1); MBAR_INIT(sb + 8, 1); }
    FENCE_ASYNC();
    __syncthreads();

    auto issue = [&](int c, int slot) {
        uint32_t mb = sb + slot * 8;
        MBAR_EXPECT(mb, STG2);
        uint32_t base = stg + slot * STG2;
        BULKCP(base,                AhiC + ((size_t)c * arows + m0) * CROW, A_ST, mb);
        BULKCP(base + A_ST,         AloC + ((size_t)c * arows + m0) * CROW, A_ST, mb);
        BULKCP(base + 2 * A_ST,         BhiC + ((size_t)c * brows + n0) * CROW, B_ST, mb);
        BULKCP(base + 2 * A_ST + B_ST,  BloC + ((size_t)c * brows + n0) * CROW, B_ST, mb);
    };

    float acc[4][8][4];
#pragma unroll
    for (int a = 0; a < 4; a++)
#pragma unroll
        for (int b = 0; b < 8; b++)
#pragma unroll
            for (int q = 0; q < 4; q++) acc[a][b][q] = 0.f;

    if (tid == 0) { issue(0, 0); issue(1, 1); }
    int ph[2] = { 0, 0 };

    for (int c = 0; c < NCHUNK; c++) {
        int st = c & 1;
        mbar_wait(sb + st * 8, ph[st]); ph[st] ^= 1;
        uint32_t sbuf = stg + st * STG2;

#pragma unroll
        for (int kk = 0; kk < 4; kk++) {
            uint32_t ah[4][4], al[4][4], bh[4][4], bl[4][4];
            uint32_t abase = sbuf + (wm * 64 + (lane & 15)) * CROW + ((lane >> 4) & 1) * 16 + kk * 32;
#pragma unroll
            for (int mi = 0; mi < 4; mi++)
                LDSM4(ah[mi][0], ah[mi][1], ah[mi][2], ah[mi][3], abase + mi * 16 * CROW);
            // B: LDSM4 covers two n8 tiles (rows r..r+7 and r+8..r+15)
            uint32_t bbase = sbuf + 2 * A_ST +
                             (wn * 64 + (lane & 7) + ((lane >> 4) & 1) * 8) * CROW +
                             ((lane >> 3) & 1) * 16 + kk * 32;
#pragma unroll
            for (int nj = 0; nj < 4; nj++)
                LDSM4(bh[nj][0], bh[nj][1], bh[nj][2], bh[nj][3], bbase + nj * 16 * CROW);
#pragma unroll
            for (int nj = 0; nj < 4; nj++)
                LDSM4(bl[nj][0], bl[nj][1], bl[nj][2], bl[nj][3], bbase + B_ST + nj * 16 * CROW);
            // hi*hi and hi*lo first (ah live), then lo A
#pragma unroll
            for (int mi = 0; mi < 4; mi++)
#pragma unroll
                for (int nj = 0; nj < 4; nj++) {
                    MMA16816(acc[mi][2 * nj],     ah[mi], &bh[nj][0]);
                    MMA16816(acc[mi][2 * nj + 1], ah[mi], &bh[nj][2]);
                    MMA16816(acc[mi][2 * nj],     ah[mi], &bl[nj][0]);
                    MMA16816(acc[mi][2 * nj + 1], ah[mi], &bl[nj][2]);
                }
#pragma unroll
            for (int mi = 0; mi < 4; mi++)
                LDSM4(al[mi][0], al[mi][1], al[mi][2], al[mi][3], abase + A_ST + mi * 16 * CROW);
#pragma unroll
            for (int mi = 0; mi < 4; mi++)
#pragma unroll
                for (int nj = 0; nj < 4; nj++) {
                    MMA16816(acc[mi][2 * nj],     al[mi], &bh[nj][0]);
                    MMA16816(acc[mi][2 * nj + 1], al[mi], &bh[nj][2]);
                }
        }
        __syncthreads();
        if (tid == 0 && c + 2 < NCHUNK) issue(c + 2, st);
    }
    __syncthreads();

    // ---- stage C through smem (256 x 132) for coalesced writeout ----
    float* Cst = (float*)smem;
#pragma unroll
    for (int mi = 0; mi < 4; mi++)
#pragma unroll
        for (int nj = 0; nj < 4; nj++)
#pragma unroll
            for (int q = 0; q < 2; q++) {
                int ni = 2 * nj + q;
                int r = wm * 64 + mi * 16 + (lane >> 2);
                int cb = wn * 64 + nj * 16 + q * 8 + (lane & 3) * 2;
                Cst[r * 132 + cb]           = acc[mi][ni][0];
                Cst[r * 132 + cb + 1]       = acc[mi][ni][1];
                Cst[(r + 8) * 132 + cb]     = acc[mi][ni][2];
                Cst[(r + 8) * 132 + cb + 1] = acc[mi][ni][3];
            }
    __syncthreads();

    for (int it = tid; it < 256 * 32; it += 256) {
        int row = it >> 5;
        int col = (it & 31) * 4;
        int m = m0 + row;
        if (mode == 1 && m >= Mact) continue;
        float4 v = *(float4*)&Cst[row * 132 + col];
        float4 b1 = *(const float4*)(bias1 + n0 + col);
        v.x += b1.x; v.y += b1.y; v.z += b1.z; v.w += b1.w;
        float* dst;
        if (mode == 0) dst = outp + (size_t)m * NG + n0 + col;
        else           dst = outp + rowout[m] + n0 + col;
        *(float4*)dst = v;
    }
}

// ---------------- step 0 ----------------
__global__ void __launch_bounds__(256) k_step0()
{
    int b = blockIdx.x;
    for (int d = threadIdx.x; d < DDIM; d += 256) {
        float4 gx = *(const float4*)&d_gatesx[(size_t)b * NG + d * 4];
        float c = sigmf(gx.x) * tanhf(gx.z);
        float h = sigmf(gx.w) * tanhf(c);
        d_c[b * DDIM + d] = c;
        __nv_bfloat16 hh = __float2bfloat16(h);
        __nv_bfloat16 hl = __float2bfloat16(h - __bfloat162float(hh));
        int ch = d >> 6, kc = d & 63;
        size_t o = ((size_t)ch * BATCH + b) * CROW + kc * 2;
        *(__nv_bfloat16*)(d_HpHi[0] + o) = hh;
        *(__nv_bfloat16*)(d_HpLo[0] + o) = hl;
    }
}

// ---------------- fused recurrent step ----------------
#define SOPA 9216
#define SOPB 18432
#define SSTG (2 * SOPA + 2 * SOPB)
#define SMEM_S (128 + 2 * SSTG)

__global__ void __launch_bounds__(256, 1) k_stepf(int s)
{
    extern __shared__ char smem[];
    int tid = threadIdx.x;
    int nt = blockIdx.x, ks = blockIdx.y;
    int n0 = nt * 128;
    int rp = (s - 1) & 1, wp = s & 1;

    uint32_t sb  = smem_u32(smem);
    uint32_t stg = sb + 128;
    int wid = tid >> 5, lane = tid & 31;
    int wm = wid & 1, wn = wid >> 1;

    if (tid == 0) { MBAR_INIT(sb + 0, 1); MBAR_INIT(sb + 8, 1); }
    FENCE_ASYNC();
    __syncthreads();

    auto issue = [&](int cc, int slot) {
        uint32_t mb = sb + slot * 8;
        int cg = ks * 4 + cc;
        MBAR_EXPECT(mb, SSTG);
        uint32_t base = stg + slot * SSTG;
        BULKCP(base,                   d_HpHi[rp] + (size_t)cg * SOPA, SOPA, mb);
        BULKCP(base + SOPA,            d_HpLo[rp] + (size_t)cg * SOPA, SOPA, mb);
        BULKCP(base + 2 * SOPA,        d_WhhHiC + ((size_t)cg * NG + n0) * CROW, SOPB, mb);
        BULKCP(base + 2 * SOPA + SOPB, d_WhhLoC + ((size_t)cg * NG + n0) * CROW, SOPB, mb);
    };

    float acc[2][4][4];
#pragma unroll
    for (int a = 0; a < 2; a++)
#pragma unroll
        for (int b = 0; b < 4; b++)
#pragma unroll
            for (int q = 0; q < 4; q++) acc[a][b][q] = 0.f;

    if (tid == 0) { issue(0, 0); issue(1, 1); }
    int ph[2] = { 0, 0 };

    for (int c = 0; c < 4; c++) {
        int st = c & 1;
        mbar_wait(sb + st * 8, ph[st]); ph[st] ^= 1;
        uint32_t sbuf = stg + st * SSTG;
#pragma unroll
        for (int kk = 0; kk < 4; kk++) {
            uint32_t ah[2][4], al[2][4], bh[4][2], bl[4][2];
            uint32_t abase = sbuf + (wm * 32 + (lane & 15)) * CROW + (lane >> 4) * 16 + kk * 32;
#pragma unroll
            for (int mi = 0; mi < 2; mi++)
                LDSM4(ah[mi][0], ah[mi][1], ah[mi][2], ah[mi][3], abase + mi * 16 * CROW);
#pragma unroll
            for (int mi = 0; mi < 2; mi++)
                LDSM4(al[mi][0], al[mi][1], al[mi][2], al[mi][3], abase + SOPA + mi * 16 * CROW);
            uint32_t bbase = sbuf + 2 * SOPA + (wn * 32 + (lane & 7)) * CROW + ((lane >> 3) & 1) * 16 + kk * 32;
#pragma unroll
            for (int ni = 0; ni < 4; ni++)
                LDSM2(bh[ni][0], bh[ni][1], bbase + ni * 8 * CROW);
#pragma unroll
            for (int ni = 0; ni < 4; ni++)
                LDSM2(bl[ni][0], bl[ni][1], bbase + SOPB + ni * 8 * CROW);
#pragma unroll
            for (int mi = 0; mi < 2; mi++)
#pragma unroll
                for (int ni = 0; ni < 4; ni++) {
                    MMA16816(acc[mi][ni], ah[mi], bh[ni]);
                    MMA16816(acc[mi][ni], al[mi], bh[ni]);
                    MMA16816(acc[mi][ni], ah[mi], bl[ni]);
                }
        }
        __syncthreads();
        if (tid == 0 && c + 2 < 4) issue(c + 2, st);
    }

#pragma unroll
    for (int mi = 0; mi < 2; mi++)
#pragma unroll
        for (int ni = 0; ni < 4; ni++) {
            int r = wm * 32 + mi * 16 + (lane >> 2);
            int col = n0 + wn * 32 + ni * 8 + (lane & 3) * 2;
            *(float2*)&d_part[ks][r][col]     = make_float2(acc[mi][ni][0], acc[mi][ni][1]);
            *(float2*)&d_part[ks][r + 8][col] = make_float2(acc[mi][ni][2], acc[mi][ni][3]);
        }
    __threadfence();
    __syncthreads();

    __shared__ int s_old;
    if (tid == 0) s_old = atomicAdd(&d_ncnt[nt], 1);
    __syncthreads();
    if (s_old != KSPLIT - 1) return;
    __threadfence();

    int cnt = d_cnt[s - 1];
    int rs  = d_rowstart[s - 1];
    int nd0 = n0 >> 2;
    for (int it = tid; it < BATCH * 32; it += 256) {
        int b = it >> 5, di = it & 31;
        int dim = nd0 + di;
        int ch = dim >> 6, kc = dim & 63;
        size_t hoff = ((size_t)ch * BATCH + b) * CROW + kc * 2;
        if (b < cnt) {
            float4 g = *(const float4*)&d_gatesx[((size_t)s * BATCH + b) * NG + dim * 4];
            float4 p0 = *(const float4*)&d_part[0][b][dim * 4];
            float4 p1 = *(const float4*)&d_part[1][b][dim * 4];
            float4 p2 = *(const float4*)&d_part[2][b][dim * 4];
            float4 p3 = *(const float4*)&d_part[3][b][dim * 4];
            float gi = g.x + p0.x + p1.x + p2.x + p3.x;
            float gf = g.y + p0.y + p1.y + p2.y + p3.y;
            float gg = g.z + p0.z + p1.z + p2.z + p3.z;
            float go = g.w + p0.w + p1.w + p2.w + p3.w;
            float cold = d_c[b * DDIM + dim];
            float cn = sigmf(gf) * cold + sigmf(gi) * tanhf(gg);
            float hn = sigmf(go) * tanhf(cn);
            d_c[b * DDIM + dim] = cn;
            __nv_bfloat16 hh = __float2bfloat16(hn);
            __nv_bfloat16 hl = __float2bfloat16(hn - __bfloat162float(hh));
            *(__nv_bfloat16*)(d_HpHi[wp] + hoff) = hh;
            *(__nv_bfloat16*)(d_HpLo[wp] + hoff) = hl;
            size_t co = ((size_t)ch * MROWS + rs + b) * CROW + kc * 2;
            *(__nv_bfloat16*)(d_HchiC + co) = hh;
            *(__nv_bfloat16*)(d_HcloC + co) = hl;
        } else {
            *(__nv_bfloat16*)(d_HpHi[wp] + hoff) = *(const __nv_bfloat16*)(d_HpHi[rp] + hoff);
            *(__nv_bfloat16*)(d_HpLo[wp] + hoff) = *(const __nv_bfloat16*)(d_HpLo[rp] + hoff);
        }
    }
    if (tid == 0) d_ncnt[nt] = 0;
}

// ---------------- launch ----------------
extern "C" void kernel_launch(void* const* d_in, const int* in_sizes, int n_in,
                              void* d_out, int out_size)
{
    const float* enc  = (const float*)d_in[0];
    const void*  caps = d_in[1];
    const void*  clen = d_in[2];
    const float* emb  = (const float*)d_in[3];
    const float* Wih  = (const float*)d_in[4];
    const float* Whh  = (const float*)d_in[5];
    const float* bih  = (const float*)d_in[6];
    const float* bhh  = (const float*)d_in[7];
    const float* fcW  = (const float*)d_in[8];
    const float* fcb  = (const float*)d_in[9];
    float* out = (float*)d_out;

    static cudaStream_t s2 = nullptr;
    static cudaEvent_t ev0 = nullptr, ev1 = nullptr, evW = nullptr;
    if (!s2) {
        cudaFuncSetAttribute(k_mma,   cudaFuncAttributeMaxDynamicSharedMemorySize, SMEMB);
        cudaFuncSetAttribute(k_stepf, cudaFuncAttributeMaxDynamicSharedMemorySize, SMEM_S);
        cudaStreamCreateWithFlags(&s2, cudaStreamNonBlocking);
        cudaEventCreateWithFlags(&ev0, cudaEventDisableTiming);
        cudaEventCreateWithFlags(&ev1, cudaEventDisableTiming);
        cudaEventCreateWithFlags(&evW, cudaEventDisableTiming);
    }

    char *pXhiC, *pXloC, *pHchiC, *pHcloC, *pWihHiC, *pWihLoC, *pWhhHiC, *pWhhLoC, *pWfcHiC, *pWfcLoC;
    float *pGatesx, *pBiasPk;
    long long* pRowout;
    int *pMact, *pM2048;
    cudaGetSymbolAddress((void**)&pXhiC, d_XhiC);
    cudaGetSymbolAddress((void**)&pXloC, d_XloC);
    cudaGetSymbolAddress((void**)&pHchiC, d_HchiC);
    cudaGetSymbolAddress((void**)&pHcloC, d_HcloC);
    cudaGetSymbolAddress((void**)&pWihHiC, d_WihHiC);
    cudaGetSymbolAddress((void**)&pWihLoC, d_WihLoC);
    cudaGetSymbolAddress((void**)&pWhhHiC, d_WhhHiC);
    cudaGetSymbolAddress((void**)&pWhhLoC, d_WhhLoC);
    cudaGetSymbolAddress((void**)&pWfcHiC, d_WfcHiC);
    cudaGetSymbolAddress((void**)&pWfcLoC, d_WfcLoC);
    cudaGetSymbolAddress((void**)&pGatesx, d_gatesx);
    cudaGetSymbolAddress((void**)&pBiasPk, d_biasPk);
    cudaGetSymbolAddress((void**)&pRowout, d_rowout);
    cudaGetSymbolAddress((void**)&pMact, d_Mact);
    cudaGetSymbolAddress((void**)&pM2048, d_M2048);

    // side stream: Whh split first (needed by step chain), then fc split + out memset
    cudaEventRecord(ev0, 0);
    cudaStreamWaitEvent(s2, ev0, 0);
    k_split<<<NG, 256, 0, s2>>>((const float4*)Whh, pWhhHiC, pWhhLoC, NG, 1);
    cudaEventRecord(evW, s2);
    k_split<<<VOCAB, 256, 0, s2>>>((const float4*)fcW, pWfcHiC, pWfcLoC, VOCAB, 0);
    cudaMemsetAsync(out, 0, (size_t)out_size * sizeof(float), s2);
    cudaEventRecord(ev1, s2);

    // main stream
    cudaMemsetAsync(pHchiC, 0, (size_t)NCHUNK * MROWS * CROW);
    cudaMemsetAsync(pHcloC, 0, (size_t)NCHUNK * MROWS * CROW);
    k_setup<<<1, 64>>>(clen);
    k_gather<<<TCAP * BATCH, 256>>>(enc, caps, emb);
    k_split<<<NG, 256>>>((const float4*)Wih, pWihHiC, pWihLoC, NG, 1);
    k_packbias<<<NG / 256, 256>>>(bih, bhh);

    // gates_x = X @ WihPk^T + biasPk   (M=2048, N=4096 packed)
    k_mma<<<dim3(8, 32), 256, SMEMB>>>(pXhiC, pXloC, pWihHiC, pWihLoC,
                                       MROWS, NG, pBiasPk, pGatesx,
                                       nullptr, pM2048, 0);

    k_step0<<<BATCH, 256>>>();
    cudaStreamWaitEvent(0, evW, 0);        // Whh split ready
    for (int s = 1; s <= TDEC; s++)
        k_stepf<<<dim3(NTILES, KSPLIT), 256, SMEM_S>>>(s);

    cudaStreamWaitEvent(0, ev1, 0);
    k_tail<<<1, 64>>>(out, out_size);

    // predictions = Hc @ fcW^T + fcb, scattered  (M=Mact compacted, N=32000)
    k_mma<<<dim3(8, 250), 256, SMEMB>>>(pHchiC, pHcloC, pWfcHiC, pWfcLoC,
                                        MROWS, VOCAB, fcb, out,
                                        pRowout, pMact, 1);
}